// round 16
// baseline (speedup 1.0000x reference)
#include <cuda_runtime.h>
#include <cuda_bf16.h>
#include <cstdint>
#include <math.h>

#define NSPK 512
#define UU   32
#define DD   512
#define NU   (NSPK*UU)
#define EPS  1e-8f

// ---------------- device scratch (no cudaMalloc allowed) ----------------
__device__ signed char g_Eq[(size_t)NU * DD];    // quantized normalized embeddings (8 MB)
__device__ signed char g_Cq[NSPK * DD];          // quantized normalized centroids (256 KB)
__device__ float       g_part[128];              // per-GEMM-block partial sums
__device__ int         g_ctr;                    // zero-init completion counter

// ---------------- PTX helpers ----------------
static __device__ __forceinline__ uint32_t smem_u32(const void* p) {
    uint32_t a;
    asm("{ .reg .u64 t; cvta.to.shared.u64 t, %1; cvt.u32.u64 %0, t; }" : "=r"(a) : "l"(p));
    return a;
}
static __device__ __forceinline__ void ldsm_x4(uint32_t& r0, uint32_t& r1,
                                               uint32_t& r2, uint32_t& r3, uint32_t addr) {
    asm volatile("ldmatrix.sync.aligned.m8n8.x4.shared.b16 {%0,%1,%2,%3}, [%4];"
                 : "=r"(r0), "=r"(r1), "=r"(r2), "=r"(r3) : "r"(addr));
}
static __device__ __forceinline__ void mma_s8(int& d0, int& d1, int& d2, int& d3,
                                              uint32_t a0, uint32_t a1, uint32_t a2, uint32_t a3,
                                              uint32_t b0, uint32_t b1) {
    asm volatile(
        "mma.sync.aligned.m16n8k32.row.col.s32.s8.s8.s32 "
        "{%0,%1,%2,%3}, {%4,%5,%6,%7}, {%8,%9}, {%0,%1,%2,%3};"
        : "+r"(d0), "+r"(d1), "+r"(d2), "+r"(d3)
        : "r"(a0), "r"(a1), "r"(a2), "r"(a3), "r"(b0), "r"(b1));
}
static __device__ __forceinline__ void cpa16(uint32_t dst, const void* gsrc) {
    unsigned long long g = (unsigned long long)__cvta_generic_to_global(gsrc);
    asm volatile("cp.async.cg.shared.global [%0], [%1], 16;" :: "r"(dst), "l"(g));
}
static __device__ __forceinline__ uint32_t pack4(float a, float b, float c, float d, float s) {
    const int q0 = __float2int_rn(a * s), q1 = __float2int_rn(b * s);
    const int q2 = __float2int_rn(c * s), q3 = __float2int_rn(d * s);
    return (q0 & 255) | ((q1 & 255) << 8) | ((q2 & 255) << 16) | ((q3 & 255) << 24);
}

// ---------------------------------------------------------------------------
// Kernel P: per-speaker pass: centroid + norm -> int8 g_Cq; per-row norms ->
// quantized rows int8 g_Eq (packed u32 stores). grid = 512, 256 thr, 64KB smem
// ---------------------------------------------------------------------------
__global__ void __launch_bounds__(256, 1) prep_kernel(const float* __restrict__ emb) {
    extern __shared__ float s[];
    __shared__ float red[9];
    const int n = blockIdx.x, tid = threadIdx.x;
    const int w = tid >> 5, lane = tid & 31;

    const float4* src = reinterpret_cast<const float4*>(emb) + (size_t)n * 4096;
    float4* s4 = reinterpret_cast<float4*>(s);
    #pragma unroll
    for (int i = 0; i < 16; i++) s4[tid + i * 256] = src[tid + i * 256];
    __syncthreads();

    float c0 = 0.f, c1 = 0.f;
    #pragma unroll
    for (int u = 0; u < UU; u++) {
        c0 += s[u * DD + tid];
        c1 += s[u * DD + tid + 256];
    }
    c0 *= (1.0f / UU); c1 *= (1.0f / UU);
    float sq = fmaf(c0, c0, c1 * c1);
    #pragma unroll
    for (int o = 16; o > 0; o >>= 1) sq += __shfl_xor_sync(0xffffffffu, sq, o);
    if (lane == 0) red[w] = sq;
    __syncthreads();
    if (tid == 0) {
        float t = 0.f;
        #pragma unroll
        for (int i = 0; i < 8; i++) t += red[i];
        red[8] = 1.0f / fmaxf(sqrtf(t), EPS);
    }
    __syncthreads();
    const float invc = red[8] * 127.0f;
    g_Cq[n * DD + tid]       = (signed char)__float2int_rn(c0 * invc);
    g_Cq[n * DD + tid + 256] = (signed char)__float2int_rn(c1 * invc);

    for (int u = w; u < UU; u += 8) {
        const float4* rowp = reinterpret_cast<const float4*>(s + u * DD);
        float4 v[4]; float ss = 0.f;
        #pragma unroll
        for (int j = 0; j < 4; j++) {
            v[j] = rowp[lane + j * 32];
            ss = fmaf(v[j].x, v[j].x, ss);
            ss = fmaf(v[j].y, v[j].y, ss);
            ss = fmaf(v[j].z, v[j].z, ss);
            ss = fmaf(v[j].w, v[j].w, ss);
        }
        #pragma unroll
        for (int o = 16; o > 0; o >>= 1) ss += __shfl_xor_sync(0xffffffffu, ss, o);
        const float qs = 127.0f / fmaxf(sqrtf(ss), EPS);
        uint32_t* dst = reinterpret_cast<uint32_t*>(g_Eq + ((size_t)n * UU + u) * DD);
        #pragma unroll
        for (int j = 0; j < 4; j++)
            dst[lane + j * 32] = pack4(v[j].x, v[j].y, v[j].z, v[j].w, qs);
    }
}

// ---------------------------------------------------------------------------
// Kernel G: int8 HMMA GEMM (m16n8k32), single wave. Block = 128 rows
// (A resident, 64KB s8); B = 16 chunks of 32 speakers in a 3-slot ring
// (3x16KB). grid = 128, 256 threads = 8 warps: 4(M) x 2(N), warp tile 32x16.
// Exact int32 dot; dequant w/127^2 in epilogue; shift-free softmax; fused
// final reduction. Rows are 512B; swizzle: 16B-seg ^= row&7 (low 3 bits).
// ---------------------------------------------------------------------------
#define SM_A   0
#define SM_B(s) (65536 + (s) * 16384)
#define SM_TOT 114688

static __device__ __forceinline__ void load_B_chunk(uint32_t sb, int c, int tid) {
    const uint32_t buf = sb + SM_B(c % 3);
    const signed char* src = g_Cq + (size_t)c * 32 * DD;
    #pragma unroll
    for (int it = 0; it < 4; it++) {
        const int u = tid + it * 256;
        const int r = u >> 5, cseg = u & 31;
        cpa16(buf + (uint32_t)(r * 512 + ((cseg ^ (r & 7)) << 4)),
              src + (size_t)r * DD + cseg * 16);
    }
    asm volatile("cp.async.commit_group;" ::: "memory");
}

__global__ void __launch_bounds__(256, 1)
gemm_loss_kernel(const float* __restrict__ wp, const float* __restrict__ bp,
                 float* __restrict__ out) {
    extern __shared__ char smem[];
    __shared__ int lastflag;
    const uint32_t sb = smem_u32(smem);
    const int tid = threadIdx.x, wid = tid >> 5, lane = tid & 31;
    const int bi = blockIdx.x;
    const int wm = wid & 3;        // row quarter (32 rows)
    const int wn = wid >> 2;       // 16-col stripe within 32-speaker chunk (0/1)
    const int l7 = lane & 7;

    // ---- prologue: A (64KB s8) + B0 (group 0), then B1 (group 1) ----
    {
        const signed char* As = g_Eq + (size_t)bi * 128 * DD;
        #pragma unroll
        for (int it = 0; it < 16; it++) {
            const int u = tid + it * 256;
            const int r = u >> 5, cseg = u & 31;
            cpa16(sb + SM_A + (uint32_t)(r * 512 + ((cseg ^ (r & 7)) << 4)),
                  As + (size_t)r * DD + cseg * 16);
        }
        const signed char* Bs = g_Cq;
        #pragma unroll
        for (int it = 0; it < 4; it++) {
            const int u = tid + it * 256;
            const int r = u >> 5, cseg = u & 31;
            cpa16(sb + SM_B(0) + (uint32_t)(r * 512 + ((cseg ^ (r & 7)) << 4)),
                  Bs + (size_t)r * DD + cseg * 16);
        }
        asm volatile("cp.async.commit_group;" ::: "memory");
        load_B_chunk(sb, 1, tid);
    }

    // ---- per-thread ldmatrix addressing (rows 512B) ----
    // A x4 mats: (m0-7,k0-15)(m8-15,k0-15)(m0-7,k16-31)(m8-15,k16-31)
    //   lane -> row = lane&15, kseg = lane>>4
    const uint32_t aoff0 = (uint32_t)(wm * 32 + (lane & 15)) * 512;       // mt=0
    const uint32_t aoff1 = aoff0 + 16 * 512;                               // mt=1
    const int ksegA = lane >> 4;
    // B x4 mats: (n0-7,k0-15)(n0-7,k16-31)(n8-15,k0-15)(n8-15,k16-31)
    //   lane -> row = wn*16 + ((lane>>4)&1)*8 + l7, kseg = (lane>>3)&1
    const uint32_t boff = (uint32_t)(wn * 16 + ((lane >> 4) & 1) * 8 + l7) * 512;
    const int ksegB = (lane >> 3) & 1;

    // diagonal bookkeeping (warp-uniform speaker index)
    const int diag = bi * 4 + wm;
    const int dchunk = diag >> 5;           // 32-speaker chunk
    const int cc = diag & 31;
    const int dwn = cc >> 4;                // 16-col stripe
    const int dj = cc & 15;
    const int dnt = dj >> 3, down = (dj & 7) >> 1, de = dj & 1;

    float os[4], od[4];
    #pragma unroll
    for (int i = 0; i < 4; i++) { os[i] = 0.f; od[i] = 0.f; }

    const float Wv = wp[0], Bv = bp[0];
    const float Sv = Wv * (1.0f / 16129.0f);   // w / 127^2

    for (int c = 0; c < 16; c++) {
        if (c < 15) asm volatile("cp.async.wait_group 1;" ::: "memory");
        else        asm volatile("cp.async.wait_group 0;" ::: "memory");
        __syncthreads();   // chunk c ready; also releases slot (c+2)%3
        if (c + 2 < 16) load_B_chunk(sb, c + 2, tid);

        const uint32_t Ab = sb + SM_A;
        const uint32_t Bb = sb + SM_B(c % 3);
        int acc[2][2][4];
        #pragma unroll
        for (int mt = 0; mt < 2; mt++)
            #pragma unroll
            for (int nt = 0; nt < 2; nt++)
                #pragma unroll
                for (int e = 0; e < 4; e++) acc[mt][nt][e] = 0;

        #pragma unroll 8
        for (int kk = 0; kk < 16; kk++) {
            const uint32_t swa = ((uint32_t)((kk * 2 + ksegA) ^ l7)) << 4;
            const uint32_t swb = ((uint32_t)((kk * 2 + ksegB) ^ l7)) << 4;
            uint32_t a[2][4], b[2][2];
            ldsm_x4(a[0][0], a[0][1], a[0][2], a[0][3], Ab + aoff0 + swa);
            ldsm_x4(a[1][0], a[1][1], a[1][2], a[1][3], Ab + aoff1 + swa);
            ldsm_x4(b[0][0], b[0][1], b[1][0], b[1][1], Bb + boff + swb);
            #pragma unroll
            for (int mt = 0; mt < 2; mt++)
                #pragma unroll
                for (int nt = 0; nt < 2; nt++)
                    mma_s8(acc[mt][nt][0], acc[mt][nt][1], acc[mt][nt][2], acc[mt][nt][3],
                           a[mt][0], a[mt][1], a[mt][2], a[mt][3], b[nt][0], b[nt][1]);
        }

        // ---- dequant + shift-free softmax accumulation (4 cols/row-set) ----
        const bool dhit = (c == dchunk) && (wn == dwn) && ((lane & 3) == down);
        #pragma unroll
        for (int mt = 0; mt < 2; mt++) {
            #pragma unroll
            for (int h = 0; h < 2; h++) {
                const int si = mt * 2 + h;
                float add = 0.f;
                #pragma unroll
                for (int nt = 0; nt < 2; nt++) {
                    const float v0 = fmaf(Sv, __int2float_rn(acc[mt][nt][h * 2 + 0]), Bv);
                    const float v1 = fmaf(Sv, __int2float_rn(acc[mt][nt][h * 2 + 1]), Bv);
                    add += __expf(v0) + __expf(v1);
                    if (dhit && nt == dnt) od[si] += (de ? v1 : v0);
                }
                os[si] += add;
            }
        }
        // next iteration's top sync protects ring-slot reuse
    }

    // ---- combine sums across the 4 lanes of each row quad ----
    #pragma unroll
    for (int si = 0; si < 4; si++) {
        #pragma unroll
        for (int off = 1; off <= 2; off <<= 1) {
            os[si] += __shfl_xor_sync(0xffffffffu, os[si], off);
            od[si] += __shfl_xor_sync(0xffffffffu, od[si], off);
        }
    }

    // ---- merge the two column-stripe warps (wid <-> wid+4) via smem ----
    float* sm_s = (float*)smem;            // [8][32]  (GEMM smem dead now)
    float* sm_d = sm_s + 256;              // [8][32]
    float* sm_r = sm_d + 256;              // partials
    __syncthreads();
    if ((lane & 3) == 0) {
        #pragma unroll
        for (int si = 0; si < 4; si++) {
            const int r = (si >> 1) * 16 + (si & 1) * 8 + (lane >> 2);
            sm_s[wid * 32 + r] = os[si];
            sm_d[wid * 32 + r] = od[si];
        }
    }
    __syncthreads();

    if (wid < 4) {   // warp wm merges its 32 rows from stripes wid and wid+4
        const float s = sm_s[wid * 32 + lane] + sm_s[(wid + 4) * 32 + lane];
        const float d = sm_d[wid * 32 + lane] + sm_d[(wid + 4) * 32 + lane];
        float local = d - __logf(s);
        #pragma unroll
        for (int o = 16; o > 0; o >>= 1)
            local += __shfl_xor_sync(0xffffffffu, local, o);
        if (lane == 0) sm_r[wid] = local;
    }
    __syncthreads();

    // ---- fused finalize: last block deterministically reduces g_part ----
    if (tid == 0) {
        g_part[bi] = sm_r[0] + sm_r[1] + sm_r[2] + sm_r[3];
        __threadfence();
        lastflag = (atomicAdd(&g_ctr, 1) == 127);
    }
    __syncthreads();
    if (lastflag) {
        float t = (tid < 128) ? g_part[tid] : 0.f;
        #pragma unroll
        for (int o = 16; o > 0; o >>= 1)
            t += __shfl_xor_sync(0xffffffffu, t, o);
        if (lane == 0) sm_r[8 + wid] = t;
        __syncthreads();
        if (tid == 0) {
            float tt = 0.f;
            #pragma unroll
            for (int i = 0; i < 8; i++) tt += sm_r[8 + i];
            out[0] = -tt * (1.0f / (float)NU);
            g_ctr = 0;   // reset for next graph replay
        }
    }
}

extern "C" void kernel_launch(void* const* d_in, const int* in_sizes, int n_in,
                              void* d_out, int out_size) {
    const float* emb = (const float*)d_in[0];
    const float* w = (const float*)d_in[1];
    const float* b = (const float*)d_in[2];
    float* out = (float*)d_out;

    cudaFuncSetAttribute(prep_kernel, cudaFuncAttributeMaxDynamicSharedMemorySize, 65536);
    cudaFuncSetAttribute(gemm_loss_kernel, cudaFuncAttributeMaxDynamicSharedMemorySize, SM_TOT);

    prep_kernel<<<NSPK, 256, 65536>>>(emb);
    gemm_loss_kernel<<<128, 256, SM_TOT>>>(w, b, out);
}

// round 17
// speedup vs baseline: 1.6106x; 1.6106x over previous
#include <cuda_runtime.h>
#include <cuda_bf16.h>
#include <cstdint>
#include <math.h>

#define NSPK 512
#define UU   32
#define DD   512
#define NU   (NSPK*UU)
#define EPS  1e-8f

// ---------------- device scratch (no cudaMalloc allowed) ----------------
__device__ __nv_bfloat16 g_Ebf[(size_t)NU * DD];   // normalized embeddings, bf16 (16 MB)
__device__ __nv_bfloat16 g_Cbf[NSPK * DD];         // normalized centroids, bf16 (0.5 MB)
__device__ float         g_part[128];              // per-GEMM-block partial sums
__device__ int           g_ctr;                    // zero-init completion counter

// ---------------- PTX helpers ----------------
static __device__ __forceinline__ uint32_t smem_u32(const void* p) {
    uint32_t a;
    asm("{ .reg .u64 t; cvta.to.shared.u64 t, %1; cvt.u32.u64 %0, t; }" : "=r"(a) : "l"(p));
    return a;
}
static __device__ __forceinline__ void ldsm_x4(uint32_t& r0, uint32_t& r1,
                                               uint32_t& r2, uint32_t& r3, uint32_t addr) {
    asm volatile("ldmatrix.sync.aligned.m8n8.x4.shared.b16 {%0,%1,%2,%3}, [%4];"
                 : "=r"(r0), "=r"(r1), "=r"(r2), "=r"(r3) : "r"(addr));
}
static __device__ __forceinline__ void mma16816(float& d0, float& d1, float& d2, float& d3,
                                                uint32_t a0, uint32_t a1, uint32_t a2, uint32_t a3,
                                                uint32_t b0, uint32_t b1) {
    asm volatile(
        "mma.sync.aligned.m16n8k16.row.col.f32.bf16.bf16.f32 "
        "{%0,%1,%2,%3}, {%4,%5,%6,%7}, {%8,%9}, {%0,%1,%2,%3};"
        : "+f"(d0), "+f"(d1), "+f"(d2), "+f"(d3)
        : "r"(a0), "r"(a1), "r"(a2), "r"(a3), "r"(b0), "r"(b1));
}
static __device__ __forceinline__ void cpa16(uint32_t dst, const void* gsrc) {
    unsigned long long g = (unsigned long long)__cvta_generic_to_global(gsrc);
    asm volatile("cp.async.cg.shared.global [%0], [%1], 16;" :: "r"(dst), "l"(g));
}

// ---------------------------------------------------------------------------
// Kernel P v2: warp-owned rows. Each warp loads its 4 rows to registers,
// computes the row norm + writes normalized bf16 immediately, and stores f32
// to smem ONLY for the centroid column pass. One smem write pass + one read
// pass (vs write+read+read before). grid = 512, 256 threads, 64KB smem.
// ---------------------------------------------------------------------------
__global__ void __launch_bounds__(256, 1) prep_kernel(const float* __restrict__ emb) {
    extern __shared__ float s[];
    __shared__ float red[9];
    const int n = blockIdx.x, tid = threadIdx.x;
    const int w = tid >> 5, lane = tid & 31;

    float4* s4 = reinterpret_cast<float4*>(s);

    // ---- pass 1: rows 4w..4w+3 -> registers -> norm -> bf16 out + STS f32
    #pragma unroll
    for (int r4 = 0; r4 < 4; r4++) {
        const int row = w * 4 + r4;
        const float4* src = reinterpret_cast<const float4*>(
            emb + ((size_t)n * UU + row) * DD);
        float4 v[4]; float ss = 0.f;
        #pragma unroll
        for (int j = 0; j < 4; j++) {
            v[j] = src[lane + j * 32];
            ss = fmaf(v[j].x, v[j].x, ss);
            ss = fmaf(v[j].y, v[j].y, ss);
            ss = fmaf(v[j].z, v[j].z, ss);
            ss = fmaf(v[j].w, v[j].w, ss);
        }
        #pragma unroll
        for (int o = 16; o > 0; o >>= 1) ss += __shfl_xor_sync(0xffffffffu, ss, o);
        const float inv = 1.0f / fmaxf(sqrtf(ss), EPS);
        uint2* dst = reinterpret_cast<uint2*>(g_Ebf + ((size_t)n * UU + row) * DD);
        #pragma unroll
        for (int j = 0; j < 4; j++) {
            __nv_bfloat162 lo = __floats2bfloat162_rn(v[j].x * inv, v[j].y * inv);
            __nv_bfloat162 hi = __floats2bfloat162_rn(v[j].z * inv, v[j].w * inv);
            uint2 pk;
            pk.x = *reinterpret_cast<uint32_t*>(&lo);
            pk.y = *reinterpret_cast<uint32_t*>(&hi);
            dst[lane + j * 32] = pk;
            s4[row * 128 + lane + j * 32] = v[j];   // raw f32 for centroid pass
        }
    }
    __syncthreads();

    // ---- pass 2: centroid (dims tid, tid+256) + normalize -> bf16
    float c0 = 0.f, c1 = 0.f;
    #pragma unroll
    for (int u = 0; u < UU; u++) {
        c0 += s[u * DD + tid];
        c1 += s[u * DD + tid + 256];
    }
    c0 *= (1.0f / UU); c1 *= (1.0f / UU);
    float sq = fmaf(c0, c0, c1 * c1);
    #pragma unroll
    for (int o = 16; o > 0; o >>= 1) sq += __shfl_xor_sync(0xffffffffu, sq, o);
    if (lane == 0) red[w] = sq;
    __syncthreads();
    if (tid == 0) {
        float t = 0.f;
        #pragma unroll
        for (int i = 0; i < 8; i++) t += red[i];
        red[8] = 1.0f / fmaxf(sqrtf(t), EPS);
    }
    __syncthreads();
    const float invc = red[8];
    g_Cbf[n * DD + tid]       = __float2bfloat16(c0 * invc);
    g_Cbf[n * DD + tid + 256] = __float2bfloat16(c1 * invc);
}

// ---------------------------------------------------------------------------
// Kernel G: HMMA GEMM (R14 structure, measured 43.4us), single wave,
// 3-stage B ring, fragment-pipelined, full kk unroll.
// Block = 128 rows (A resident, 128KB); B = 16 chunks of 32 speakers.
// grid = 128, 256 threads = 8 warps: 4(M) x 2(N), warp tile 32x16.
// Shift-free softmax, fused final reduction.
// ---------------------------------------------------------------------------
#define SM_A   0
#define SM_B(s) (131072 + (s) * 32768)
#define SM_TOT 229376
#define SWZ_OFF(r, cb) ((uint32_t)((r) * 1024 + ((((cb)) ^ ((r) & 7)) << 4)))

static __device__ __forceinline__ void load_B_chunk(uint32_t sb, int c, int tid) {
    const uint32_t buf = sb + SM_B(c % 3);
    const __nv_bfloat16* src = g_Cbf + (size_t)c * 32 * DD;
    #pragma unroll
    for (int it = 0; it < 8; it++) {
        const int u = tid + it * 256;
        const int r = u >> 6, cb = u & 63;
        cpa16(buf + SWZ_OFF(r, cb), src + (size_t)r * DD + cb * 8);
    }
    asm volatile("cp.async.commit_group;" ::: "memory");
}

__global__ void __launch_bounds__(256, 1)
gemm_loss_kernel(const float* __restrict__ wp, const float* __restrict__ bp,
                 float* __restrict__ out) {
    extern __shared__ char smem[];
    __shared__ int lastflag;
    const uint32_t sb = smem_u32(smem);
    const int tid = threadIdx.x, wid = tid >> 5, lane = tid & 31;
    const int bi = blockIdx.x;
    const int wm = wid & 3;        // row quarter (32 rows)
    const int wn = wid >> 2;       // 16-col stripe within 32-speaker chunk (0/1)
    const int l7 = lane & 7;

    // ---- prologue: A + B0 (group 0), then B1 (group 1) ----
    {
        const __nv_bfloat16* As = g_Ebf + (size_t)bi * 128 * DD;
        #pragma unroll
        for (int it = 0; it < 32; it++) {
            const int u = tid + it * 256;
            const int r = u >> 6, cb = u & 63;
            cpa16(sb + SM_A + SWZ_OFF(r, cb), As + (size_t)r * DD + cb * 8);
        }
        const __nv_bfloat16* Bs = g_Cbf;
        #pragma unroll
        for (int it = 0; it < 8; it++) {
            const int u = tid + it * 256;
            const int r = u >> 6, cb = u & 63;
            cpa16(sb + SM_B(0) + SWZ_OFF(r, cb), Bs + (size_t)r * DD + cb * 8);
        }
        asm volatile("cp.async.commit_group;" ::: "memory");
        load_B_chunk(sb, 1, tid);
    }

    // per-thread ldmatrix addressing
    const uint32_t aoff0 = sb + SM_A + (uint32_t)(wm * 32 + (lane & 15)) * 1024;
    const uint32_t aoff1 = aoff0 + 16 * 1024;
    const int cbA = lane >> 4;              // A k-half select
    const int khB = (lane >> 3) & 1;        // B k-half select (x4 form)
    const uint32_t brow = (uint32_t)((wn * 16 + (lane >> 4) * 8 + l7) * 1024);

    // diagonal bookkeeping (warp-uniform speaker index)
    const int diag = bi * 4 + wm;
    const int dchunk = diag >> 5;
    const int cc = diag & 31;
    const int dwn = cc >> 4;
    const int dj = cc & 15;
    const int dnt = dj >> 3, down = (dj & 7) >> 1, de = dj & 1;

    float os[4], od[4];
    #pragma unroll
    for (int i = 0; i < 4; i++) { os[i] = 0.f; od[i] = 0.f; }

    const float Wv = wp[0], Bv = bp[0];

    for (int c = 0; c < 16; c++) {
        if (c < 15) asm volatile("cp.async.wait_group 1;" ::: "memory");
        else        asm volatile("cp.async.wait_group 0;" ::: "memory");
        __syncthreads();   // chunk c ready; also releases slot (c+2)%3
        if (c + 2 < 16) load_B_chunk(sb, c + 2, tid);

        const uint32_t Bbuf = sb + SM_B(c % 3);
        float acc[2][2][4];
        #pragma unroll
        for (int mt = 0; mt < 2; mt++)
            #pragma unroll
            for (int nt = 0; nt < 2; nt++)
                #pragma unroll
                for (int e = 0; e < 4; e++) acc[mt][nt][e] = 0.f;

        // ---- fragment-pipelined kk loop (ping/pong register buffers) ----
        uint32_t af[2][2][4], bf[2][2][2];
        {   // preload kk = 0
            const int cb = 0;
            ldsm_x4(af[0][0][0], af[0][0][1], af[0][0][2], af[0][0][3],
                    aoff0 + ((uint32_t)((cb + cbA) ^ l7) << 4));
            ldsm_x4(af[0][1][0], af[0][1][1], af[0][1][2], af[0][1][3],
                    aoff1 + ((uint32_t)((cb + cbA) ^ l7) << 4));
            ldsm_x4(bf[0][0][0], bf[0][0][1], bf[0][1][0], bf[0][1][1],
                    Bbuf + brow + ((uint32_t)((cb + khB) ^ l7) << 4));
        }
        #pragma unroll
        for (int kk = 0; kk < 32; kk++) {
            const int p = kk & 1, q = p ^ 1;
            if (kk < 31) {   // prefetch kk+1 into the other buffer
                const int cb = (kk + 1) * 2;
                ldsm_x4(af[q][0][0], af[q][0][1], af[q][0][2], af[q][0][3],
                        aoff0 + ((uint32_t)((cb + cbA) ^ l7) << 4));
                ldsm_x4(af[q][1][0], af[q][1][1], af[q][1][2], af[q][1][3],
                        aoff1 + ((uint32_t)((cb + cbA) ^ l7) << 4));
                ldsm_x4(bf[q][0][0], bf[q][0][1], bf[q][1][0], bf[q][1][1],
                        Bbuf + brow + ((uint32_t)((cb + khB) ^ l7) << 4));
            }
            #pragma unroll
            for (int mt = 0; mt < 2; mt++)
                #pragma unroll
                for (int nt = 0; nt < 2; nt++)
                    mma16816(acc[mt][nt][0], acc[mt][nt][1], acc[mt][nt][2], acc[mt][nt][3],
                             af[p][mt][0], af[p][mt][1], af[p][mt][2], af[p][mt][3],
                             bf[p][nt][0], bf[p][nt][1]);
        }

        // ---- shift-free softmax accumulation (4 cols per row-set) ----
        const bool dhit = (c == dchunk) && (wn == dwn) && ((lane & 3) == down);
        #pragma unroll
        for (int mt = 0; mt < 2; mt++) {
            #pragma unroll
            for (int h = 0; h < 2; h++) {
                const int si = mt * 2 + h;
                float add = 0.f;
                #pragma unroll
                for (int nt = 0; nt < 2; nt++) {
                    const float v0 = fmaf(Wv, acc[mt][nt][h * 2 + 0], Bv);
                    const float v1 = fmaf(Wv, acc[mt][nt][h * 2 + 1], Bv);
                    add += __expf(v0) + __expf(v1);
                    if (dhit && nt == dnt) od[si] += (de ? v1 : v0);
                }
                os[si] += add;
            }
        }
        // next iteration's top sync protects ring-slot reuse
    }

    // ---- combine sums across the 4 lanes of each row quad ----
    #pragma unroll
    for (int si = 0; si < 4; si++) {
        #pragma unroll
        for (int off = 1; off <= 2; off <<= 1) {
            os[si] += __shfl_xor_sync(0xffffffffu, os[si], off);
            od[si] += __shfl_xor_sync(0xffffffffu, od[si], off);
        }
    }

    // ---- merge the two column-stripe warps (wid <-> wid+4) via smem ----
    float* sm_s = (float*)smem;            // [8][32]  (GEMM smem dead now)
    float* sm_d = sm_s + 256;              // [8][32]
    float* sm_r = sm_d + 256;              // partials
    __syncthreads();
    if ((lane & 3) == 0) {
        #pragma unroll
        for (int si = 0; si < 4; si++) {
            const int r = (si >> 1) * 16 + (si & 1) * 8 + (lane >> 2);
            sm_s[wid * 32 + r] = os[si];
            sm_d[wid * 32 + r] = od[si];
        }
    }
    __syncthreads();

    if (wid < 4) {   // warp wm merges its 32 rows from stripes wid and wid+4
        const float s = sm_s[wid * 32 + lane] + sm_s[(wid + 4) * 32 + lane];
        const float d = sm_d[wid * 32 + lane] + sm_d[(wid + 4) * 32 + lane];
        float local = d - __logf(s);
        #pragma unroll
        for (int o = 16; o > 0; o >>= 1)
            local += __shfl_xor_sync(0xffffffffu, local, o);
        if (lane == 0) sm_r[wid] = local;
    }
    __syncthreads();

    // ---- fused finalize: last block deterministically reduces g_part ----
    if (tid == 0) {
        g_part[bi] = sm_r[0] + sm_r[1] + sm_r[2] + sm_r[3];
        __threadfence();
        lastflag = (atomicAdd(&g_ctr, 1) == 127);
    }
    __syncthreads();
    if (lastflag) {
        float t = (tid < 128) ? g_part[tid] : 0.f;
        #pragma unroll
        for (int o = 16; o > 0; o >>= 1)
            t += __shfl_xor_sync(0xffffffffu, t, o);
        if (lane == 0) sm_r[8 + wid] = t;
        __syncthreads();
        if (tid == 0) {
            float tt = 0.f;
            #pragma unroll
            for (int i = 0; i < 8; i++) tt += sm_r[8 + i];
            out[0] = -tt * (1.0f / (float)NU);
            g_ctr = 0;   // reset for next graph replay
        }
    }
}

extern "C" void kernel_launch(void* const* d_in, const int* in_sizes, int n_in,
                              void* d_out, int out_size) {
    const float* emb = (const float*)d_in[0];
    const float* w = (const float*)d_in[1];
    const float* b = (const float*)d_in[2];
    float* out = (float*)d_out;

    cudaFuncSetAttribute(prep_kernel, cudaFuncAttributeMaxDynamicSharedMemorySize, 65536);
    cudaFuncSetAttribute(gemm_loss_kernel, cudaFuncAttributeMaxDynamicSharedMemorySize, SM_TOT);

    prep_kernel<<<NSPK, 256, 65536>>>(emb);
    gemm_loss_kernel<<<128, 256, SM_TOT>>>(w, b, out);
}